// round 1
// baseline (speedup 1.0000x reference)
#include <cuda_runtime.h>
#include <cuda_bf16.h>
#include <cstdint>
#include <math_constants.h>

#define NROWS 8192
#define KDIM  768

// Scratch (allocation-free rule: __device__ globals)
__device__ __nv_bfloat16 g_xn[NROWS * KDIM];   // normalized ex, bf16
__device__ __nv_bfloat16 g_yn[NROWS * KDIM];   // normalized ey, bf16
__device__ float g_rowmax[NROWS];

// ---------------------------------------------------------------------------
// Kernel 0: init row maxima
// ---------------------------------------------------------------------------
__global__ void init_rowmax_kernel() {
    int i = blockIdx.x * 256 + threadIdx.x;
    if (i < NROWS) g_rowmax[i] = -CUDART_INF_F;
}

// ---------------------------------------------------------------------------
// Kernel 1: row-normalize fp32 -> bf16. One warp per row.
// ---------------------------------------------------------------------------
__global__ void normalize_kernel(const float* __restrict__ src, int which) {
    __nv_bfloat16* dst = which ? g_yn : g_xn;
    int warp = (blockIdx.x * blockDim.x + threadIdx.x) >> 5;
    int lane = threadIdx.x & 31;
    if (warp >= NROWS) return;

    const float4* p = reinterpret_cast<const float4*>(src + (size_t)warp * KDIM);
    float4 v[6];
    float s = 0.f;
#pragma unroll
    for (int i = 0; i < 6; i++) {
        v[i] = p[i * 32 + lane];
        s += v[i].x * v[i].x + v[i].y * v[i].y + v[i].z * v[i].z + v[i].w * v[i].w;
    }
#pragma unroll
    for (int o = 16; o > 0; o >>= 1) s += __shfl_xor_sync(0xffffffffu, s, o);

    float inv = (s > 0.f) ? (1.0f / sqrtf(s)) : 0.f;

    __nv_bfloat162* d2 = reinterpret_cast<__nv_bfloat162*>(dst + (size_t)warp * KDIM);
#pragma unroll
    for (int i = 0; i < 6; i++) {
        float2 lo = make_float2(v[i].x * inv, v[i].y * inv);
        float2 hi = make_float2(v[i].z * inv, v[i].w * inv);
        d2[(i * 32 + lane) * 2]     = __float22bfloat162_rn(lo);
        d2[(i * 32 + lane) * 2 + 1] = __float22bfloat162_rn(hi);
    }
}

// ---------------------------------------------------------------------------
// Kernel 2: bf16 GEMM (x_hat @ y_hat^T) with fused row-max reduction.
// Block tile 128(M) x 128(N) x 64(K). 8 warps: 4(M) x 2(N), warp tile 32x64.
// mma.sync.m16n8k16.bf16, SW128-swizzled smem, ldmatrix.
// ---------------------------------------------------------------------------
__device__ __forceinline__ void atomicMaxF(float* addr, float v) {
    if (v >= 0.f) atomicMax((int*)addr, __float_as_int(v));
    else          atomicMin((unsigned int*)addr, __float_as_uint(v));
}

__global__ __launch_bounds__(256, 2) void gemm_rowmax_kernel() {
    __shared__ __align__(1024) __nv_bfloat16 sA[128 * 64];
    __shared__ __align__(1024) __nv_bfloat16 sB[128 * 64];

    const int tid  = threadIdx.x;
    const int lane = tid & 31;
    const int warp = tid >> 5;
    const int wm = warp >> 1;   // 0..3  (M direction, 32 rows each)
    const int wn = warp & 1;    // 0..1  (N direction, 64 cols each)
    const int mbase = blockIdx.x * 128;
    const int nbase = blockIdx.y * 128;

    float acc[2][8][4];
#pragma unroll
    for (int i = 0; i < 2; i++)
#pragma unroll
        for (int j = 0; j < 8; j++)
#pragma unroll
            for (int c = 0; c < 4; c++) acc[i][j][c] = 0.f;

    uint32_t sAu = (uint32_t)__cvta_generic_to_shared(sA);
    uint32_t sBu = (uint32_t)__cvta_generic_to_shared(sB);

    const int ldrow = tid >> 1;          // 0..127
    const int ldc0  = (tid & 1) * 4;     // 16B-chunk base (0 or 4)

    for (int k0 = 0; k0 < KDIM; k0 += 64) {
        // ---- global -> shared (SW128 swizzle), 64B per thread per tile ----
#pragma unroll
        for (int c = 0; c < 4; c++) {
            int chunk = ldc0 + c;   // 0..7, 16 bytes each (8 bf16)
            uint4 va = *reinterpret_cast<const uint4*>(
                &g_xn[(size_t)(mbase + ldrow) * KDIM + k0 + chunk * 8]);
            uint4 vb = *reinterpret_cast<const uint4*>(
                &g_yn[(size_t)(nbase + ldrow) * KDIM + k0 + chunk * 8]);
            int off = ldrow * 128 + chunk * 16;
            off ^= (off >> 3) & 0x70;   // SW128
            *reinterpret_cast<uint4*>(reinterpret_cast<char*>(sA) + off) = va;
            *reinterpret_cast<uint4*>(reinterpret_cast<char*>(sB) + off) = vb;
        }
        __syncthreads();

        // ---- 4 x k16 MMA steps ----
#pragma unroll
        for (int ks = 0; ks < 4; ks++) {
            const int kk = ks * 16;

            uint32_t a[2][4];
#pragma unroll
            for (int mi = 0; mi < 2; mi++) {
                int r  = wm * 32 + mi * 16 + (lane & 15);
                int kc = kk + ((lane >> 4) << 3);
                int off = r * 128 + kc * 2;
                off ^= (off >> 3) & 0x70;
                uint32_t addr = sAu + off;
                asm volatile("ldmatrix.sync.aligned.m8n8.x4.shared.b16 {%0,%1,%2,%3}, [%4];"
                             : "=r"(a[mi][0]), "=r"(a[mi][1]), "=r"(a[mi][2]), "=r"(a[mi][3])
                             : "r"(addr));
            }

            uint32_t b[8][2];
#pragma unroll
            for (int np = 0; np < 4; np++) {
                int n  = wn * 64 + np * 16 + (lane & 7) + ((lane >> 4) << 3);
                int kc = kk + (((lane >> 3) & 1) << 3);
                int off = n * 128 + kc * 2;
                off ^= (off >> 3) & 0x70;
                uint32_t addr = sBu + off;
                asm volatile("ldmatrix.sync.aligned.m8n8.x4.shared.b16 {%0,%1,%2,%3}, [%4];"
                             : "=r"(b[2 * np][0]), "=r"(b[2 * np][1]),
                               "=r"(b[2 * np + 1][0]), "=r"(b[2 * np + 1][1])
                             : "r"(addr));
            }

#pragma unroll
            for (int mi = 0; mi < 2; mi++)
#pragma unroll
                for (int nt = 0; nt < 8; nt++) {
                    asm volatile(
                        "mma.sync.aligned.m16n8k16.row.col.f32.bf16.bf16.f32 "
                        "{%0,%1,%2,%3}, {%4,%5,%6,%7}, {%8,%9}, {%0,%1,%2,%3};"
                        : "+f"(acc[mi][nt][0]), "+f"(acc[mi][nt][1]),
                          "+f"(acc[mi][nt][2]), "+f"(acc[mi][nt][3])
                        : "r"(a[mi][0]), "r"(a[mi][1]), "r"(a[mi][2]), "r"(a[mi][3]),
                          "r"(b[nt][0]), "r"(b[nt][1]));
                }
        }
        __syncthreads();
    }

    // ---- epilogue: per-row max over this block's 128 columns -> global ----
#pragma unroll
    for (int mi = 0; mi < 2; mi++) {
        float r0 = -CUDART_INF_F, r1 = -CUDART_INF_F;
#pragma unroll
        for (int nt = 0; nt < 8; nt++) {
            r0 = fmaxf(r0, fmaxf(acc[mi][nt][0], acc[mi][nt][1]));
            r1 = fmaxf(r1, fmaxf(acc[mi][nt][2], acc[mi][nt][3]));
        }
        // reduce across the quad (lane%4 spans columns)
#pragma unroll
        for (int o = 1; o <= 2; o <<= 1) {
            r0 = fmaxf(r0, __shfl_xor_sync(0xffffffffu, r0, o));
            r1 = fmaxf(r1, __shfl_xor_sync(0xffffffffu, r1, o));
        }
        if ((lane & 3) == 0) {
            int row = mbase + wm * 32 + mi * 16 + (lane >> 2);
            atomicMaxF(&g_rowmax[row], r0);
            atomicMaxF(&g_rowmax[row + 8], r1);
        }
    }
}

// ---------------------------------------------------------------------------
// Kernel 3: lp = Normal(1, 0.3).log_prob(max); out = sum(exp(lp)*lp).
// Single block, deterministic reduction (double accumulation).
// ---------------------------------------------------------------------------
__global__ void finalize_kernel(float* out) {
    __shared__ double red[256];
    double s = 0.0;
    for (int i = threadIdx.x; i < NROWS; i += 256) {
        float m = g_rowmax[i];
        float z = (m - 1.0f) * (1.0f / 0.3f);
        // -0.5 z^2 - log(0.3) - 0.5 log(2*pi) = -0.5 z^2 + 0.2850342711212634
        float lp = fmaf(-0.5f * z, z, 0.2850342711212634f);
        s += (double)(expf(lp) * lp);
    }
    red[threadIdx.x] = s;
    __syncthreads();
    for (int o = 128; o > 0; o >>= 1) {
        if (threadIdx.x < o) red[threadIdx.x] += red[threadIdx.x + o];
        __syncthreads();
    }
    if (threadIdx.x == 0) out[0] = (float)red[0];
}

// ---------------------------------------------------------------------------
extern "C" void kernel_launch(void* const* d_in, const int* in_sizes, int n_in,
                              void* d_out, int out_size) {
    const float* ex = (const float*)d_in[0];
    const float* ey = (const float*)d_in[1];
    float* out = (float*)d_out;

    init_rowmax_kernel<<<NROWS / 256, 256>>>();
    normalize_kernel<<<NROWS / 8, 256>>>(ex, 0);
    normalize_kernel<<<NROWS / 8, 256>>>(ey, 1);

    dim3 grid(NROWS / 128, NROWS / 128);   // 64 x 64 tiles
    gemm_rowmax_kernel<<<grid, 256>>>();

    finalize_kernel<<<1, 256>>>(out);
}

// round 3
// speedup vs baseline: 1.5755x; 1.5755x over previous
#include <cuda_runtime.h>
#include <cuda_bf16.h>
#include <cstdint>
#include <math_constants.h>

#define NROWS 8192
#define KDIM  768

// ---------------- scratch (__device__ globals; no allocations) -------------
__device__ __nv_bfloat16 g_xn[NROWS * KDIM];
__device__ __nv_bfloat16 g_yn[NROWS * KDIM];
__device__ float g_rowmax[NROWS];

// ---------------------------------------------------------------------------
__global__ void init_rowmax_kernel() {
    int i = blockIdx.x * 256 + threadIdx.x;
    if (i < NROWS) g_rowmax[i] = -CUDART_INF_F;
}

// one warp per row: fp32 -> normalized bf16
__global__ void normalize_kernel(const float* __restrict__ src, int which) {
    __nv_bfloat16* dst = which ? g_yn : g_xn;
    int warp = (blockIdx.x * blockDim.x + threadIdx.x) >> 5;
    int lane = threadIdx.x & 31;
    if (warp >= NROWS) return;

    const float4* p = reinterpret_cast<const float4*>(src + (size_t)warp * KDIM);
    float4 v[6];
    float s = 0.f;
#pragma unroll
    for (int i = 0; i < 6; i++) {
        v[i] = p[i * 32 + lane];
        s += v[i].x * v[i].x + v[i].y * v[i].y + v[i].z * v[i].z + v[i].w * v[i].w;
    }
#pragma unroll
    for (int o = 16; o > 0; o >>= 1) s += __shfl_xor_sync(0xffffffffu, s, o);
    float inv = (s > 0.f) ? (1.0f / sqrtf(s)) : 0.f;

    __nv_bfloat162* d2 = reinterpret_cast<__nv_bfloat162*>(dst + (size_t)warp * KDIM);
#pragma unroll
    for (int i = 0; i < 6; i++) {
        float2 lo = make_float2(v[i].x * inv, v[i].y * inv);
        float2 hi = make_float2(v[i].z * inv, v[i].w * inv);
        d2[(i * 32 + lane) * 2]     = __float22bfloat162_rn(lo);
        d2[(i * 32 + lane) * 2 + 1] = __float22bfloat162_rn(hi);
    }
}

__device__ __forceinline__ void atomicMaxF(float* addr, float v) {
    if (v >= 0.f) atomicMax((int*)addr, __float_as_int(v));
    else          atomicMin((unsigned int*)addr, __float_as_uint(v));
}

// ---------------- smem layout: 4 stages, K-chunk 64 (128B rows, SW128) -----
#define STAGES 4
#define A_STAGE_BYTES (128 * 128)          // 16 KB
#define B_STAGE_BYTES (256 * 128)          // 32 KB
#define SA_OFF(s) ((s) * A_STAGE_BYTES)
#define SB_OFF(s) (STAGES * A_STAGE_BYTES + (s) * B_STAGE_BYTES)
#define SMEM_TOTAL (STAGES * (A_STAGE_BYTES + B_STAGE_BYTES))   // 192 KB

// issue cp.async for one stage: A 128 rows, B 256 rows, 64 bf16 columns
__device__ __forceinline__ void load_stage(uint32_t aBase, uint32_t bBase,
                                           int mbase, int nbase, int k0, int tid) {
#pragma unroll
    for (int j = 0; j < 4; j++) {            // A: 1024 16B chunks / 256 thr
        int idx = j * 256 + tid;
        int row = idx >> 3, ck = idx & 7;
        int off = row * 128 + ck * 16;
        off ^= (off >> 3) & 0x70;
        const void* src = &g_xn[(size_t)(mbase + row) * KDIM + k0 + ck * 8];
        asm volatile("cp.async.cg.shared.global [%0], [%1], 16;"
                     :: "r"(aBase + off), "l"(src));
    }
#pragma unroll
    for (int j = 0; j < 8; j++) {            // B: 2048 16B chunks / 256 thr
        int idx = j * 256 + tid;
        int row = idx >> 3, ck = idx & 7;
        int off = row * 128 + ck * 16;
        off ^= (off >> 3) & 0x70;
        const void* src = &g_yn[(size_t)(nbase + row) * KDIM + k0 + ck * 8];
        asm volatile("cp.async.cg.shared.global [%0], [%1], 16;"
                     :: "r"(bBase + off), "l"(src));
    }
}

// ---------------------------------------------------------------------------
// GEMM + fused row-max. Block 128(M) x 256(N), 8 warps as 2(M) x 4(N),
// warp tile 64x64, mma.sync.m16n8k16.bf16, 4-stage cp.async pipeline.
// ---------------------------------------------------------------------------
__global__ void __launch_bounds__(256, 1) gemm_rowmax_kernel() {
    extern __shared__ char smem[];
    const uint32_t sbase = (uint32_t)__cvta_generic_to_shared(smem);

    const int tid  = threadIdx.x;
    const int lane = tid & 31;
    const int warp = tid >> 5;
    const int wm = warp & 1;        // 0..1 : 64 M-rows each
    const int wn = warp >> 1;       // 0..3 : 64 N-cols each
    const int mbase = blockIdx.x * 128;
    const int nbase = blockIdx.y * 256;

    float acc[4][8][4];
#pragma unroll
    for (int i = 0; i < 4; i++)
#pragma unroll
        for (int j = 0; j < 8; j++)
#pragma unroll
            for (int c = 0; c < 4; c++) acc[i][j][c] = 0.f;

    const int NIT = KDIM / 64;      // 12

    // prologue: stages 0..2
#pragma unroll
    for (int s = 0; s < 3; s++) {
        load_stage(sbase + SA_OFF(s), sbase + SB_OFF(s), mbase, nbase, s * 64, tid);
        asm volatile("cp.async.commit_group;" ::: "memory");
    }

    // precompute per-thread ldmatrix swizzled offsets (stage-relative)
    int aoff[4], boff[4];
#pragma unroll
    for (int mi = 0; mi < 4; mi++) {
        int r  = wm * 64 + mi * 16 + (lane & 15);
        int kc = (lane >> 4) << 3;
        int off = r * 128 + kc * 2;
        aoff[mi] = off ^ ((off >> 3) & 0x70);
    }
#pragma unroll
    for (int np = 0; np < 4; np++) {
        int n  = wn * 64 + np * 16 + (lane & 7) + ((lane >> 4) << 3);
        int kc = ((lane >> 3) & 1) << 3;
        int off = n * 128 + kc * 2;
        boff[np] = off ^ ((off >> 3) & 0x70);
    }

    for (int i = 0; i < NIT; i++) {
        if (i + 2 < NIT)      { asm volatile("cp.async.wait_group 2;" ::: "memory"); }
        else if (i + 2 == NIT){ asm volatile("cp.async.wait_group 1;" ::: "memory"); }
        else                  { asm volatile("cp.async.wait_group 0;" ::: "memory"); }
        __syncthreads();

        if (i + 3 < NIT) {
            int s = (i + 3) & 3;
            load_stage(sbase + SA_OFF(s), sbase + SB_OFF(s),
                       mbase, nbase, (i + 3) * 64, tid);
            asm volatile("cp.async.commit_group;" ::: "memory");
        }

        const uint32_t aS = sbase + SA_OFF(i & 3);
        const uint32_t bS = sbase + SB_OFF(i & 3);

#pragma unroll
        for (int ks = 0; ks < 4; ks++) {
            // k-step advances 16 cols = 32B; swizzle XOR pattern depends only on
            // row bits, so adding 32B to a swizzled offset stays correct when the
            // 32B step doesn't carry into bit7+ : kc*2 in [0,128), steps of 32. OK.
            const int kb = ks * 32;

            uint32_t a[4][4];
#pragma unroll
            for (int mi = 0; mi < 4; mi++) {
                uint32_t addr = aS + (uint32_t)(aoff[mi] ^ kb);
                asm volatile("ldmatrix.sync.aligned.m8n8.x4.shared.b16 {%0,%1,%2,%3}, [%4];"
                             : "=r"(a[mi][0]), "=r"(a[mi][1]),
                               "=r"(a[mi][2]), "=r"(a[mi][3]) : "r"(addr));
            }
            uint32_t b[8][2];
#pragma unroll
            for (int np = 0; np < 4; np++) {
                uint32_t addr = bS + (uint32_t)(boff[np] ^ kb);
                asm volatile("ldmatrix.sync.aligned.m8n8.x4.shared.b16 {%0,%1,%2,%3}, [%4];"
                             : "=r"(b[2 * np][0]), "=r"(b[2 * np][1]),
                               "=r"(b[2 * np + 1][0]), "=r"(b[2 * np + 1][1])
                             : "r"(addr));
            }
#pragma unroll
            for (int mi = 0; mi < 4; mi++)
#pragma unroll
                for (int nt = 0; nt < 8; nt++) {
                    asm volatile(
                        "mma.sync.aligned.m16n8k16.row.col.f32.bf16.bf16.f32 "
                        "{%0,%1,%2,%3}, {%4,%5,%6,%7}, {%8,%9}, {%0,%1,%2,%3};"
                        : "+f"(acc[mi][nt][0]), "+f"(acc[mi][nt][1]),
                          "+f"(acc[mi][nt][2]), "+f"(acc[mi][nt][3])
                        : "r"(a[mi][0]), "r"(a[mi][1]), "r"(a[mi][2]), "r"(a[mi][3]),
                          "r"(b[nt][0]), "r"(b[nt][1]));
                }
        }
        __syncthreads();
    }

    // ---- epilogue: per-row max over this block's 256 columns ----
#pragma unroll
    for (int mi = 0; mi < 4; mi++) {
        float r0 = -CUDART_INF_F, r1 = -CUDART_INF_F;
#pragma unroll
        for (int nt = 0; nt < 8; nt++) {
            r0 = fmaxf(r0, fmaxf(acc[mi][nt][0], acc[mi][nt][1]));
            r1 = fmaxf(r1, fmaxf(acc[mi][nt][2], acc[mi][nt][3]));
        }
#pragma unroll
        for (int o = 1; o <= 2; o <<= 1) {
            r0 = fmaxf(r0, __shfl_xor_sync(0xffffffffu, r0, o));
            r1 = fmaxf(r1, __shfl_xor_sync(0xffffffffu, r1, o));
        }
        if ((lane & 3) == 0) {
            int row = mbase + wm * 64 + mi * 16 + (lane >> 2);
            atomicMaxF(&g_rowmax[row], r0);
            atomicMaxF(&g_rowmax[row + 8], r1);
        }
    }
}

// ---------------------------------------------------------------------------
__global__ void finalize_kernel(float* out) {
    __shared__ double red[256];
    double s = 0.0;
    for (int i = threadIdx.x; i < NROWS; i += 256) {
        float mv = g_rowmax[i];
        float z = (mv - 1.0f) * (1.0f / 0.3f);
        float lp = fmaf(-0.5f * z, z, 0.2850342711212634f);
        s += (double)(expf(lp) * lp);
    }
    red[threadIdx.x] = s;
    __syncthreads();
    for (int o = 128; o > 0; o >>= 1) {
        if (threadIdx.x < o) red[threadIdx.x] += red[threadIdx.x + o];
        __syncthreads();
    }
    if (threadIdx.x == 0) out[0] = (float)red[0];
}

// ---------------------------------------------------------------------------
extern "C" void kernel_launch(void* const* d_in, const int* in_sizes, int n_in,
                              void* d_out, int out_size) {
    const float* ex = (const float*)d_in[0];
    const float* ey = (const float*)d_in[1];
    float* out = (float*)d_out;

    cudaFuncSetAttribute(gemm_rowmax_kernel,
                         cudaFuncAttributeMaxDynamicSharedMemorySize, SMEM_TOTAL);

    init_rowmax_kernel<<<NROWS / 256, 256>>>();
    normalize_kernel<<<NROWS / 8, 256>>>(ex, 0);
    normalize_kernel<<<NROWS / 8, 256>>>(ey, 1);

    dim3 grid(NROWS / 128, NROWS / 256);   // 64 x 32
    gemm_rowmax_kernel<<<grid, 256, SMEM_TOTAL>>>();

    finalize_kernel<<<1, 256>>>(out);
}

// round 4
// speedup vs baseline: 1.6458x; 1.0447x over previous
#include <cuda_runtime.h>
#include <cuda_bf16.h>
#include <cstdint>
#include <math_constants.h>

#define NROWS 8192
#define KDIM  768

// ---------------- scratch (__device__ globals; no allocations) -------------
__device__ __nv_bfloat16 g_xn[NROWS * KDIM];
__device__ __nv_bfloat16 g_yn[NROWS * KDIM];
__device__ float g_rowmax[NROWS];

// ---------------------------------------------------------------------------
// one warp per row: fp32 -> normalized bf16 (also inits g_rowmax when which==0)
__global__ void normalize_kernel(const float* __restrict__ src, int which) {
    __nv_bfloat16* dst = which ? g_yn : g_xn;
    int warp = (blockIdx.x * blockDim.x + threadIdx.x) >> 5;
    int lane = threadIdx.x & 31;
    if (warp >= NROWS) return;

    if (which == 0 && lane == 0) g_rowmax[warp] = -CUDART_INF_F;

    const float4* p = reinterpret_cast<const float4*>(src + (size_t)warp * KDIM);
    float4 v[6];
    float s = 0.f;
#pragma unroll
    for (int i = 0; i < 6; i++) {
        v[i] = p[i * 32 + lane];
        s += v[i].x * v[i].x + v[i].y * v[i].y + v[i].z * v[i].z + v[i].w * v[i].w;
    }
#pragma unroll
    for (int o = 16; o > 0; o >>= 1) s += __shfl_xor_sync(0xffffffffu, s, o);
    float inv = (s > 0.f) ? (1.0f / sqrtf(s)) : 0.f;

    __nv_bfloat162* d2 = reinterpret_cast<__nv_bfloat162*>(dst + (size_t)warp * KDIM);
#pragma unroll
    for (int i = 0; i < 6; i++) {
        float2 lo = make_float2(v[i].x * inv, v[i].y * inv);
        float2 hi = make_float2(v[i].z * inv, v[i].w * inv);
        d2[(i * 32 + lane) * 2]     = __float22bfloat162_rn(lo);
        d2[(i * 32 + lane) * 2 + 1] = __float22bfloat162_rn(hi);
    }
}

__device__ __forceinline__ void atomicMaxF(float* addr, float v) {
    if (v >= 0.f) atomicMax((int*)addr, __float_as_int(v));
    else          atomicMin((unsigned int*)addr, __float_as_uint(v));
}

// ---------------- smem: 4 stages, K-chunk 64 (128B rows, SW128) ------------
#define STAGES 4
#define A_STAGE_BYTES (128 * 128)          // 16 KB
#define B_STAGE_BYTES (256 * 128)          // 32 KB
#define SA_OFF(s) ((s) * A_STAGE_BYTES)
#define SB_OFF(s) (STAGES * A_STAGE_BYTES + (s) * B_STAGE_BYTES)
#define SMEM_TOTAL (STAGES * (A_STAGE_BYTES + B_STAGE_BYTES))   // 192 KB

// issue cp.async for one stage: A 128 rows, B 256 rows, 64 bf16 cols. 512 thr.
__device__ __forceinline__ void load_stage(uint32_t aBase, uint32_t bBase,
                                           int mbase, int nbase, int k0, int tid) {
#pragma unroll
    for (int j = 0; j < 2; j++) {            // A: 1024 16B chunks / 512 thr
        int idx = j * 512 + tid;
        int row = idx >> 3, ck = idx & 7;
        int off = row * 128 + ck * 16;
        off ^= (off >> 3) & 0x70;
        const void* src = &g_xn[(size_t)(mbase + row) * KDIM + k0 + ck * 8];
        asm volatile("cp.async.cg.shared.global [%0], [%1], 16;"
                     :: "r"(aBase + off), "l"(src));
    }
#pragma unroll
    for (int j = 0; j < 4; j++) {            // B: 2048 16B chunks / 512 thr
        int idx = j * 512 + tid;
        int row = idx >> 3, ck = idx & 7;
        int off = row * 128 + ck * 16;
        off ^= (off >> 3) & 0x70;
        const void* src = &g_yn[(size_t)(nbase + row) * KDIM + k0 + ck * 8];
        asm volatile("cp.async.cg.shared.global [%0], [%1], 16;"
                     :: "r"(bBase + off), "l"(src));
    }
}

// ---------------------------------------------------------------------------
// GEMM + fused row-max. Block 128(M) x 256(N), 16 warps as 4(M) x 4(N),
// warp tile 32x64, mma.sync.m16n8k16.bf16, 4-stage cp.async, 1 sync/iter.
// ---------------------------------------------------------------------------
__global__ void __launch_bounds__(512, 1) gemm_rowmax_kernel() {
    extern __shared__ char smem[];
    const uint32_t sbase = (uint32_t)__cvta_generic_to_shared(smem);

    const int tid  = threadIdx.x;
    const int lane = tid & 31;
    const int warp = tid >> 5;
    const int wm = warp & 3;        // 0..3 : 32 M-rows each
    const int wn = warp >> 2;       // 0..3 : 64 N-cols each
    const int mbase = blockIdx.x * 128;
    const int nbase = blockIdx.y * 256;

    float acc[2][8][4];
#pragma unroll
    for (int i = 0; i < 2; i++)
#pragma unroll
        for (int j = 0; j < 8; j++)
#pragma unroll
            for (int c = 0; c < 4; c++) acc[i][j][c] = 0.f;

    const int NIT = KDIM / 64;      // 12

    // prologue: stages 0..2
#pragma unroll
    for (int s = 0; s < 3; s++) {
        load_stage(sbase + SA_OFF(s), sbase + SB_OFF(s), mbase, nbase, s * 64, tid);
        asm volatile("cp.async.commit_group;" ::: "memory");
    }

    // per-thread swizzled ldmatrix offsets (stage-relative)
    int aoff[2], boff[4];
#pragma unroll
    for (int mi = 0; mi < 2; mi++) {
        int r  = wm * 32 + mi * 16 + (lane & 15);
        int kc = (lane >> 4) << 3;
        int off = r * 128 + kc * 2;
        aoff[mi] = off ^ ((off >> 3) & 0x70);
    }
#pragma unroll
    for (int np = 0; np < 4; np++) {
        int n  = wn * 64 + np * 16 + (lane & 7) + ((lane >> 4) << 3);
        int kc = ((lane >> 3) & 1) << 3;
        int off = n * 128 + kc * 2;
        boff[np] = off ^ ((off >> 3) & 0x70);
    }

    for (int i = 0; i < NIT; i++) {
        if (i + 2 < NIT)      { asm volatile("cp.async.wait_group 2;" ::: "memory"); }
        else if (i + 2 == NIT){ asm volatile("cp.async.wait_group 1;" ::: "memory"); }
        else                  { asm volatile("cp.async.wait_group 0;" ::: "memory"); }
        __syncthreads();   // single barrier per iter: data ready + prev stage free

        if (i + 3 < NIT) {
            int s = (i + 3) & 3;
            load_stage(sbase + SA_OFF(s), sbase + SB_OFF(s),
                       mbase, nbase, (i + 3) * 64, tid);
            asm volatile("cp.async.commit_group;" ::: "memory");
        }

        const uint32_t aS = sbase + SA_OFF(i & 3);
        const uint32_t bS = sbase + SB_OFF(i & 3);

#pragma unroll
        for (int ks = 0; ks < 4; ks++) {
            const int kb = ks * 32;   // 16 cols = 32B; XORs correctly under SW128

            uint32_t a[2][4];
#pragma unroll
            for (int mi = 0; mi < 2; mi++) {
                uint32_t addr = aS + (uint32_t)(aoff[mi] ^ kb);
                asm volatile("ldmatrix.sync.aligned.m8n8.x4.shared.b16 {%0,%1,%2,%3}, [%4];"
                             : "=r"(a[mi][0]), "=r"(a[mi][1]),
                               "=r"(a[mi][2]), "=r"(a[mi][3]) : "r"(addr));
            }
            uint32_t b[8][2];
#pragma unroll
            for (int np = 0; np < 4; np++) {
                uint32_t addr = bS + (uint32_t)(boff[np] ^ kb);
                asm volatile("ldmatrix.sync.aligned.m8n8.x4.shared.b16 {%0,%1,%2,%3}, [%4];"
                             : "=r"(b[2 * np][0]), "=r"(b[2 * np][1]),
                               "=r"(b[2 * np + 1][0]), "=r"(b[2 * np + 1][1])
                             : "r"(addr));
            }
#pragma unroll
            for (int mi = 0; mi < 2; mi++)
#pragma unroll
                for (int nt = 0; nt < 8; nt++) {
                    asm volatile(
                        "mma.sync.aligned.m16n8k16.row.col.f32.bf16.bf16.f32 "
                        "{%0,%1,%2,%3}, {%4,%5,%6,%7}, {%8,%9}, {%0,%1,%2,%3};"
                        : "+f"(acc[mi][nt][0]), "+f"(acc[mi][nt][1]),
                          "+f"(acc[mi][nt][2]), "+f"(acc[mi][nt][3])
                        : "r"(a[mi][0]), "r"(a[mi][1]), "r"(a[mi][2]), "r"(a[mi][3]),
                          "r"(b[nt][0]), "r"(b[nt][1]));
                }
        }
    }

    // ---- epilogue: per-row max over this block's 256 columns ----
#pragma unroll
    for (int mi = 0; mi < 2; mi++) {
        float r0 = -CUDART_INF_F, r1 = -CUDART_INF_F;
#pragma unroll
        for (int nt = 0; nt < 8; nt++) {
            r0 = fmaxf(r0, fmaxf(acc[mi][nt][0], acc[mi][nt][1]));
            r1 = fmaxf(r1, fmaxf(acc[mi][nt][2], acc[mi][nt][3]));
        }
#pragma unroll
        for (int o = 1; o <= 2; o <<= 1) {
            r0 = fmaxf(r0, __shfl_xor_sync(0xffffffffu, r0, o));
            r1 = fmaxf(r1, __shfl_xor_sync(0xffffffffu, r1, o));
        }
        if ((lane & 3) == 0) {
            int row = mbase + wm * 32 + mi * 16 + (lane >> 2);
            atomicMaxF(&g_rowmax[row], r0);
            atomicMaxF(&g_rowmax[row + 8], r1);
        }
    }
}

// ---------------------------------------------------------------------------
__global__ void finalize_kernel(float* out) {
    __shared__ double red[256];
    double s = 0.0;
    for (int i = threadIdx.x; i < NROWS; i += 256) {
        float mv = g_rowmax[i];
        float z = (mv - 1.0f) * (1.0f / 0.3f);
        float lp = fmaf(-0.5f * z, z, 0.2850342711212634f);
        s += (double)(expf(lp) * lp);
    }
    red[threadIdx.x] = s;
    __syncthreads();
    for (int o = 128; o > 0; o >>= 1) {
        if (threadIdx.x < o) red[threadIdx.x] += red[threadIdx.x + o];
        __syncthreads();
    }
    if (threadIdx.x == 0) out[0] = (float)red[0];
}

// ---------------------------------------------------------------------------
extern "C" void kernel_launch(void* const* d_in, const int* in_sizes, int n_in,
                              void* d_out, int out_size) {
    const float* ex = (const float*)d_in[0];
    const float* ey = (const float*)d_in[1];
    float* out = (float*)d_out;

    cudaFuncSetAttribute(gemm_rowmax_kernel,
                         cudaFuncAttributeMaxDynamicSharedMemorySize, SMEM_TOTAL);

    normalize_kernel<<<NROWS / 8, 256>>>(ex, 0);
    normalize_kernel<<<NROWS / 8, 256>>>(ey, 1);

    dim3 grid(NROWS / 128, NROWS / 256);   // 64 x 32
    gemm_rowmax_kernel<<<grid, 512, SMEM_TOTAL>>>();

    finalize_kernel<<<1, 256>>>(out);
}

// round 11
// speedup vs baseline: 1.7266x; 1.0491x over previous
#include <cuda_runtime.h>
#include <cuda_bf16.h>
#include <cstdint>
#include <math_constants.h>

#define NROWS 8192
#define KDIM  768

// ---------------- scratch (__device__ globals; no allocations) -------------
__device__ __nv_bfloat16 g_xn[NROWS * KDIM];
__device__ __nv_bfloat16 g_yn[NROWS * KDIM];
__device__ float g_rowmax[NROWS];

// ---------------------------------------------------------------------------
// one warp per row: fp32 -> normalized bf16 (also inits g_rowmax when which==0)
__global__ void normalize_kernel(const float* __restrict__ src, int which) {
    __nv_bfloat16* dst = which ? g_yn : g_xn;
    int warp = (blockIdx.x * blockDim.x + threadIdx.x) >> 5;
    int lane = threadIdx.x & 31;
    if (warp >= NROWS) return;

    if (which == 0 && lane == 0) g_rowmax[warp] = -CUDART_INF_F;

    const float4* p = reinterpret_cast<const float4*>(src + (size_t)warp * KDIM);
    float4 v[6];
    float s = 0.f;
#pragma unroll
    for (int i = 0; i < 6; i++) {
        v[i] = p[i * 32 + lane];
        s += v[i].x * v[i].x + v[i].y * v[i].y + v[i].z * v[i].z + v[i].w * v[i].w;
    }
#pragma unroll
    for (int o = 16; o > 0; o >>= 1) s += __shfl_xor_sync(0xffffffffu, s, o);
    float inv = (s > 0.f) ? (1.0f / sqrtf(s)) : 0.f;

    __nv_bfloat162* d2 = reinterpret_cast<__nv_bfloat162*>(dst + (size_t)warp * KDIM);
#pragma unroll
    for (int i = 0; i < 6; i++) {
        float2 lo = make_float2(v[i].x * inv, v[i].y * inv);
        float2 hi = make_float2(v[i].z * inv, v[i].w * inv);
        d2[(i * 32 + lane) * 2]     = __float22bfloat162_rn(lo);
        d2[(i * 32 + lane) * 2 + 1] = __float22bfloat162_rn(hi);
    }
}

__device__ __forceinline__ void atomicMaxF(float* addr, float v) {
    if (v >= 0.f) atomicMax((int*)addr, __float_as_int(v));
    else          atomicMin((unsigned int*)addr, __float_as_uint(v));
}

// ---------------- smem: 3 stages, K-chunk 64 (128B rows, SW128) ------------
// Block tile 128x128 -> A stage 16KB + B stage 16KB; 3 stages = 96KB.
// Two CTAs co-resident per SM (2 x 96KB smem, <=128 regs/thread).
#define STAGES 3
#define A_STAGE_BYTES (128 * 128)
#define B_STAGE_BYTES (128 * 128)
#define SA_OFF(s) ((s) * A_STAGE_BYTES)
#define SB_OFF(s) (STAGES * A_STAGE_BYTES + (s) * B_STAGE_BYTES)
#define SMEM_TOTAL (STAGES * (A_STAGE_BYTES + B_STAGE_BYTES))   // 96 KB

// issue cp.async for one stage: A 128 rows, B 128 rows, 64 bf16 cols. 256 thr.
__device__ __forceinline__ void load_stage(uint32_t aBase, uint32_t bBase,
                                           int mbase, int nbase, int k0, int tid) {
#pragma unroll
    for (int j = 0; j < 4; j++) {            // A: 1024 16B chunks / 256 thr
        int idx = j * 256 + tid;
        int row = idx >> 3, ck = idx & 7;
        int off = row * 128 + ck * 16;
        off ^= (off >> 3) & 0x70;
        const void* src = &g_xn[(size_t)(mbase + row) * KDIM + k0 + ck * 8];
        asm volatile("cp.async.cg.shared.global [%0], [%1], 16;"
                     :: "r"(aBase + off), "l"(src));
    }
#pragma unroll
    for (int j = 0; j < 4; j++) {            // B: 1024 16B chunks / 256 thr
        int idx = j * 256 + tid;
        int row = idx >> 3, ck = idx & 7;
        int off = row * 128 + ck * 16;
        off ^= (off >> 3) & 0x70;
        const void* src = &g_yn[(size_t)(nbase + row) * KDIM + k0 + ck * 8];
        asm volatile("cp.async.cg.shared.global [%0], [%1], 16;"
                     :: "r"(bBase + off), "l"(src));
    }
}

// ---------------------------------------------------------------------------
// GEMM + fused row-max. Block 128(M) x 128(N), 8 warps as 4(M) x 2(N),
// warp tile 32x64, mma.sync.m16n8k16.bf16, 3-stage cp.async, occupancy 2.
// ---------------------------------------------------------------------------
__global__ void __launch_bounds__(256, 2) gemm_rowmax_kernel() {
    extern __shared__ char smem[];
    const uint32_t sbase = (uint32_t)__cvta_generic_to_shared(smem);

    const int tid  = threadIdx.x;
    const int lane = tid & 31;
    const int warp = tid >> 5;
    const int wm = warp & 3;        // 0..3 : 32 M-rows each
    const int wn = warp >> 2;       // 0..1 : 64 N-cols each
    const int mbase = blockIdx.x * 128;
    const int nbase = blockIdx.y * 128;

    float acc[2][8][4];
#pragma unroll
    for (int i = 0; i < 2; i++)
#pragma unroll
        for (int j = 0; j < 8; j++)
#pragma unroll
            for (int c = 0; c < 4; c++) acc[i][j][c] = 0.f;

    const int NIT = KDIM / 64;      // 12

    // prologue: stages 0,1 <- chunks 0,1
#pragma unroll
    for (int s = 0; s < 2; s++) {
        load_stage(sbase + SA_OFF(s), sbase + SB_OFF(s), mbase, nbase, s * 64, tid);
        asm volatile("cp.async.commit_group;" ::: "memory");
    }

    // per-thread swizzled ldmatrix offsets (stage-relative)
    int aoff[2], boff[4];
#pragma unroll
    for (int mi = 0; mi < 2; mi++) {
        int r  = wm * 32 + mi * 16 + (lane & 15);
        int kc = (lane >> 4) << 3;
        int off = r * 128 + kc * 2;
        aoff[mi] = off ^ ((off >> 3) & 0x70);
    }
#pragma unroll
    for (int np = 0; np < 4; np++) {
        int n  = wn * 64 + np * 16 + (lane & 7) + ((lane >> 4) << 3);
        int kc = ((lane >> 3) & 1) << 3;
        int off = n * 128 + kc * 2;
        boff[np] = off ^ ((off >> 3) & 0x70);
    }

    for (int i = 0; i < NIT; i++) {
        if (i + 1 < NIT) { asm volatile("cp.async.wait_group 1;" ::: "memory"); }
        else             { asm volatile("cp.async.wait_group 0;" ::: "memory"); }
        __syncthreads();   // chunk i ready everywhere; stage (i+2)%3 free

        if (i + 2 < NIT) {
            int s = (i + 2) % 3;
            load_stage(sbase + SA_OFF(s), sbase + SB_OFF(s),
                       mbase, nbase, (i + 2) * 64, tid);
            asm volatile("cp.async.commit_group;" ::: "memory");
        }

        const uint32_t aS = sbase + SA_OFF(i % 3);
        const uint32_t bS = sbase + SB_OFF(i % 3);

#pragma unroll
        for (int ks = 0; ks < 4; ks++) {
            const int kb = ks * 32;   // 16 cols = 32B; XOR-safe under SW128

            uint32_t a[2][4];
#pragma unroll
            for (int mi = 0; mi < 2; mi++) {
                uint32_t addr = aS + (uint32_t)(aoff[mi] ^ kb);
                asm volatile("ldmatrix.sync.aligned.m8n8.x4.shared.b16 {%0,%1,%2,%3}, [%4];"
                             : "=r"(a[mi][0]), "=r"(a[mi][1]),
                               "=r"(a[mi][2]), "=r"(a[mi][3]) : "r"(addr));
            }
            uint32_t b[8][2];
#pragma unroll
            for (int np = 0; np < 4; np++) {
                uint32_t addr = bS + (uint32_t)(boff[np] ^ kb);
                asm volatile("ldmatrix.sync.aligned.m8n8.x4.shared.b16 {%0,%1,%2,%3}, [%4];"
                             : "=r"(b[2 * np][0]), "=r"(b[2 * np][1]),
                               "=r"(b[2 * np + 1][0]), "=r"(b[2 * np + 1][1])
                             : "r"(addr));
            }
#pragma unroll
            for (int mi = 0; mi < 2; mi++)
#pragma unroll
                for (int nt = 0; nt < 8; nt++) {
                    asm volatile(
                        "mma.sync.aligned.m16n8k16.row.col.f32.bf16.bf16.f32 "
                        "{%0,%1,%2,%3}, {%4,%5,%6,%7}, {%8,%9}, {%0,%1,%2,%3};"
                        : "+f"(acc[mi][nt][0]), "+f"(acc[mi][nt][1]),
                          "+f"(acc[mi][nt][2]), "+f"(acc[mi][nt][3])
                        : "r"(a[mi][0]), "r"(a[mi][1]), "r"(a[mi][2]), "r"(a[mi][3]),
                          "r"(b[nt][0]), "r"(b[nt][1]));
                }
        }
    }

    // ---- epilogue: per-row max over this block's 128 columns ----
#pragma unroll
    for (int mi = 0; mi < 2; mi++) {
        float r0 = -CUDART_INF_F, r1 = -CUDART_INF_F;
#pragma unroll
        for (int nt = 0; nt < 8; nt++) {
            r0 = fmaxf(r0, fmaxf(acc[mi][nt][0], acc[mi][nt][1]));
            r1 = fmaxf(r1, fmaxf(acc[mi][nt][2], acc[mi][nt][3]));
        }
#pragma unroll
        for (int o = 1; o <= 2; o <<= 1) {
            r0 = fmaxf(r0, __shfl_xor_sync(0xffffffffu, r0, o));
            r1 = fmaxf(r1, __shfl_xor_sync(0xffffffffu, r1, o));
        }
        if ((lane & 3) == 0) {
            int row = mbase + wm * 32 + mi * 16 + (lane >> 2);
            atomicMaxF(&g_rowmax[row], r0);
            atomicMaxF(&g_rowmax[row + 8], r1);
        }
    }
}

// ---------------------------------------------------------------------------
// 1024 threads, float4 loads, warp-shuffle + smem reduce (deterministic).
__global__ void finalize_kernel(float* out) {
    __shared__ double red[32];
    const int tid = threadIdx.x;
    double s = 0.0;
    const float4* rm = reinterpret_cast<const float4*>(g_rowmax);
#pragma unroll
    for (int j = 0; j < 2; j++) {
        float4 v = rm[j * 1024 + tid];
        float mv[4] = {v.x, v.y, v.z, v.w};
#pragma unroll
        for (int c = 0; c < 4; c++) {
            float z = (mv[c] - 1.0f) * (1.0f / 0.3f);
            float lp = fmaf(-0.5f * z, z, 0.2850342711212634f);
            s += (double)(expf(lp) * lp);
        }
    }
#pragma unroll
    for (int o = 16; o > 0; o >>= 1) s += __shfl_xor_sync(0xffffffffu, s, o);
    if ((tid & 31) == 0) red[tid >> 5] = s;
    __syncthreads();
    if (tid < 32) {
        double t = red[tid];
#pragma unroll
        for (int o = 16; o > 0; o >>= 1) t += __shfl_xor_sync(0xffffffffu, t, o);
        if (tid == 0) out[0] = (float)t;
    }
}

// ---------------------------------------------------------------------------
extern "C" void kernel_launch(void* const* d_in, const int* in_sizes, int n_in,
                              void* d_out, int out_size) {
    const float* ex = (const float*)d_in[0];
    const float* ey = (const float*)d_in[1];
    float* out = (float*)d_out;

    cudaFuncSetAttribute(gemm_rowmax_kernel,
                         cudaFuncAttributeMaxDynamicSharedMemorySize, SMEM_TOTAL);

    normalize_kernel<<<NROWS / 8, 256>>>(ex, 0);
    normalize_kernel<<<NROWS / 8, 256>>>(ey, 1);

    dim3 grid(NROWS / 128, NROWS / 128);   // 64 x 64
    gemm_rowmax_kernel<<<grid, 256, SMEM_TOTAL>>>();

    finalize_kernel<<<1, 1024>>>(out);
}